// round 1
// baseline (speedup 1.0000x reference)
#include <cuda_runtime.h>
#include <math.h>

// Problem constants
#define BB 4
#define CC 3
#define HH 384
#define WW 384
#define HWSZ (HH * WW)
#define CHW (CC * HWSZ)
#define HALF 3

#define SIGMA_COLOR 0.1f
#define SIGMA_SPACE 7.0f
#define LP_P 0.8f
#define EPS_LP 1e-6f

#define INV2SC (1.0f / (2.0f * SIGMA_COLOR * SIGMA_COLOR))   // 50
#define INV2SS (1.0f / (2.0f * SIGMA_SPACE * SIGMA_SPACE))   // 1/98

// w_space table: index (dy+3)*7 + (dx+3)
__device__ float g_ws[49];

__global__ void init_kernel(float* out) {
    int t = threadIdx.x;
    if (t == 0) out[0] = 0.0f;
    if (t < 49) {
        int dy = t / 7 - 3;
        int dx = t % 7 - 3;
        g_ws[t] = expf(-(float)(dy * dy + dx * dx) * INV2SS);
    }
}

// lp(d) = (d*d + eps)^(p/2) with p=0.8 -> (d*d+eps)^0.4
__device__ __forceinline__ float lp_term(float d) {
    float t = fmaf(d, d, EPS_LP);
    // __powf = exp2(0.4 * log2(t)); t > 0 always
    return __powf(t, 0.4f);
}

__global__ __launch_bounds__(256)
void loss_kernel(const float* __restrict__ inp,
                 const float* __restrict__ tgt,
                 float* __restrict__ out) {
    const int x = blockIdx.x * 32 + threadIdx.x;
    const int y = blockIdx.y * 8 + threadIdx.y;
    const int b = blockIdx.z;

    const float* ib = inp + b * CHW;
    const float* tb = tgt + b * CHW;

    const int pidx = y * WW + x;

    // center values (3 channels, both tensors)
    const float i0 = ib[pidx];
    const float i1 = ib[pidx + HWSZ];
    const float i2 = ib[pidx + 2 * HWSZ];
    const float t0 = tb[pidx];
    const float t1 = tb[pidx + HWSZ];
    const float t2 = tb[pidx + 2 * HWSZ];

    // L2 term contribution of this pixel (all channels)
    float acc = (i0 - t0) * (i0 - t0)
              + (i1 - t1) * (i1 - t1)
              + (i2 - t2) * (i2 - t2);

    for (int dy = -HALF; dy <= HALF; dy++) {
        int qy = y + dy;
        qy = qy < 0 ? 0 : (qy >= HH ? HH - 1 : qy);
        const int rowbase = qy * WW;
        const float sdy = (float)(dy * dy);
#pragma unroll
        for (int dx = -HALF; dx <= HALF; dx++) {
            if (dy == 0 && dx == 0) continue;
            int qx = x + dx;
            qx = qx < 0 ? 0 : (qx >= WW ? WW - 1 : qx);
            const int q = rowbase + qx;

            const float iq0 = __ldg(ib + q);
            const float iq1 = __ldg(ib + q + HWSZ);
            const float iq2 = __ldg(ib + q + 2 * HWSZ);
            const float tq0 = __ldg(tb + q);
            const float tq1 = __ldg(tb + q + HWSZ);
            const float tq2 = __ldg(tb + q + 2 * HWSZ);

            const float d0 = i0 - iq0, d1 = i1 - iq1, d2 = i2 - iq2;
            const float e0 = t0 - tq0, e1 = t1 - tq1, e2 = t2 - tq2;

            const float cd = fmaf(e0, e0, fmaf(e1, e1, e2 * e2));
            const float sdist = sdy + (float)(dx * dx);

            // ws = exp(-sdist*inv2ss) from table; wcs = ws * wc in ONE exp
            const float ws  = g_ws[(dy + 3) * 7 + (dx + 3)];
            const float wcs = __expf(-fmaf(cd, INV2SC, sdist * INV2SS));

            const float sm = lp_term(d0) + lp_term(d1) + lp_term(d2);

            const float a0 = fabsf(d0) - fabsf(e0);
            const float a1 = fabsf(d1) - fabsf(e1);
            const float a2 = fabsf(d2) - fabsf(e2);
            const float ed = lp_term(a0) + lp_term(a1) + lp_term(a2);

            acc = fmaf(wcs, sm, acc);
            acc = fmaf(ws - wcs, ed, acc);
        }
    }

    // ---- reduction: warp shuffle, then block, then one atomic ----
    const unsigned FULL = 0xFFFFFFFFu;
#pragma unroll
    for (int off = 16; off > 0; off >>= 1)
        acc += __shfl_down_sync(FULL, acc, off);

    __shared__ float warp_sums[8];
    const int tid = threadIdx.y * 32 + threadIdx.x;
    const int wid = tid >> 5;
    const int lid = tid & 31;
    if (lid == 0) warp_sums[wid] = acc;
    __syncthreads();

    if (wid == 0) {
        float v = (lid < 8) ? warp_sums[lid] : 0.0f;
#pragma unroll
        for (int off = 4; off > 0; off >>= 1)
            v += __shfl_down_sync(FULL, v, off);
        if (lid == 0) {
            const float inv_n = 1.0f / (float)(BB * CC * HH * WW);
            atomicAdd(out, v * inv_n);
        }
    }
}

extern "C" void kernel_launch(void* const* d_in, const int* in_sizes, int n_in,
                              void* d_out, int out_size) {
    const float* inp = (const float*)d_in[0];
    const float* tgt = (const float*)d_in[1];
    float* out = (float*)d_out;

    init_kernel<<<1, 64>>>(out);

    dim3 block(32, 8, 1);
    dim3 grid(WW / 32, HH / 8, BB);
    loss_kernel<<<grid, block>>>(inp, tgt, out);
}

// round 2
// speedup vs baseline: 1.5332x; 1.5332x over previous
#include <cuda_runtime.h>
#include <math.h>

#define BB 4
#define CC 3
#define HH 384
#define WW 384
#define HWSZ (HH * WW)
#define CHW (CC * HWSZ)
#define HALF 3

#define INV2SC 50.0f            // 1/(2*0.1^2)
#define INV2SS (1.0f / 98.0f)   // 1/(2*7^2)
#define EPS_LP 1e-6f

// Border pixels per image: 2 strips of 3x384 + 378 rows x 6 cols
#define NBORDER (2 * 3 * WW + (HH - 6) * 6)   // 4572
#define NBTOT (NBORDER * BB)                  // 18288

// exp(-k*k/98) for k=0..3
__device__ float g_wsk[4];

__global__ void init_kernel(float* out) {
    int t = threadIdx.x;
    if (t == 0) out[0] = 0.0f;
    if (t < 4) g_wsk[t] = expf(-(float)(t * t) * INV2SS);
}

__device__ __forceinline__ float lp_term(float d) {
    // (d*d + eps)^0.4
    return __powf(fmaf(d, d, EPS_LP), 0.4f);
}

// warp -> block reduction, one atomic per block (pre-scaled by 1/n)
__device__ __forceinline__ void reduce_add(float acc, float* out, int tid) {
    const unsigned FULL = 0xFFFFFFFFu;
#pragma unroll
    for (int off = 16; off > 0; off >>= 1)
        acc += __shfl_down_sync(FULL, acc, off);
    __shared__ float wsum[8];
    const int wid = tid >> 5, lid = tid & 31;
    if (lid == 0) wsum[wid] = acc;
    __syncthreads();
    if (wid == 0) {
        float v = (lid < 8) ? wsum[lid] : 0.0f;
#pragma unroll
        for (int off = 4; off > 0; off >>= 1)
            v += __shfl_down_sync(FULL, v, off);
        if (lid == 0) {
            const float inv_n = 1.0f / (float)(BB * CC * HH * WW);
            atomicAdd(out, v * inv_n);
        }
    }
}

// Main kernel: all pixels, 24-offset half-set (dy>0, or dy==0 && dx>0),
// in-bounds neighbors only; each term counted twice (exact pair symmetry).
__global__ __launch_bounds__(256)
void pair_kernel(const float* __restrict__ inp,
                 const float* __restrict__ tgt,
                 float* __restrict__ out) {
    const int x = blockIdx.x * 32 + threadIdx.x;
    const int y = blockIdx.y * 8 + threadIdx.y;
    const int b = blockIdx.z;
    const int pidx = y * WW + x;

    const float* pi = inp + b * CHW + pidx;
    const float* pt = tgt + b * CHW + pidx;

    const float i0 = pi[0], i1 = pi[HWSZ], i2 = pi[2 * HWSZ];
    const float t0 = pt[0], t1 = pt[HWSZ], t2 = pt[2 * HWSZ];

    // spatial weight components exp(-k^2/98); indexed with unroll constants
    float wky[4];
    wky[0] = 1.0f;
    wky[1] = g_wsk[1];
    wky[2] = g_wsk[2];
    wky[3] = g_wsk[3];

    float pacc = 0.0f;

#pragma unroll
    for (int dy = 0; dy <= 3; dy++) {
        const bool vy = (y + dy) < HH;
        const int dx0 = (dy == 0) ? 1 : -3;
#pragma unroll
        for (int dx = -3; dx <= 3; dx++) {
            if (dx < dx0) continue;            // resolved at compile time
            const bool v = vy && ((unsigned)(x + dx) < (unsigned)WW);
            if (v) {
                const int q = dy * WW + dx;    // compile-time immediate
                const float iq0 = __ldg(pi + q);
                const float iq1 = __ldg(pi + q + HWSZ);
                const float iq2 = __ldg(pi + q + 2 * HWSZ);
                const float tq0 = __ldg(pt + q);
                const float tq1 = __ldg(pt + q + HWSZ);
                const float tq2 = __ldg(pt + q + 2 * HWSZ);

                const float d0 = i0 - iq0, d1 = i1 - iq1, d2 = i2 - iq2;
                const float e0 = t0 - tq0, e1 = t1 - tq1, e2 = t2 - tq2;

                const float cd = fmaf(e0, e0, fmaf(e1, e1, e2 * e2));
                const int adx = dx < 0 ? -dx : dx;
                const float ws = wky[dy] * wky[adx];
                const float sconst = (float)(dy * dy + dx * dx) * INV2SS;
                const float wcs = __expf(-fmaf(cd, INV2SC, sconst)); // ws*wc fused

                const float sm = lp_term(d0) + lp_term(d1) + lp_term(d2);
                const float ed = lp_term(fabsf(d0) - fabsf(e0))
                               + lp_term(fabsf(d1) - fabsf(e1))
                               + lp_term(fabsf(d2) - fabsf(e2));

                pacc = fmaf(wcs, sm, pacc);
                pacc = fmaf(ws - wcs, ed, pacc);
            }
        }
    }

    const float l2 = (i0 - t0) * (i0 - t0)
                   + (i1 - t1) * (i1 - t1)
                   + (i2 - t2) * (i2 - t2);
    const float acc = fmaf(2.0f, pacc, l2);

    reduce_add(acc, out, threadIdx.y * 32 + threadIdx.x);
}

// Border kernel: only the clamped (out-of-bounds) ordered terms, weight 1.
__global__ __launch_bounds__(256)
void border_kernel(const float* __restrict__ inp,
                   const float* __restrict__ tgt,
                   float* __restrict__ out) {
    const int gid = blockIdx.x * 256 + threadIdx.x;
    float acc = 0.0f;

    if (gid < NBTOT) {
        const int b = gid / NBORDER;
        const int r = gid % NBORDER;
        int x, y;
        if (r < 3 * WW) {                    // top rows 0..2
            y = r / WW; x = r % WW;
        } else if (r < 6 * WW) {             // bottom rows 381..383
            const int r2 = r - 3 * WW;
            y = (HH - 3) + r2 / WW; x = r2 % WW;
        } else {                             // side cols, rows 3..380
            const int r3 = r - 6 * WW;
            y = 3 + r3 / 6;
            const int c = r3 % 6;
            x = (c < 3) ? c : (WW - 6 + c);  // 0,1,2 or 381,382,383
        }
        const int pidx = y * WW + x;
        const float* pi = inp + b * CHW + pidx;
        const float* pt = tgt + b * CHW + pidx;

        const float i0 = pi[0], i1 = pi[HWSZ], i2 = pi[2 * HWSZ];
        const float t0 = pt[0], t1 = pt[HWSZ], t2 = pt[2 * HWSZ];

        float wky[4];
        wky[0] = 1.0f;
        wky[1] = g_wsk[1];
        wky[2] = g_wsk[2];
        wky[3] = g_wsk[3];

#pragma unroll
        for (int dy = -3; dy <= 3; dy++) {
#pragma unroll
            for (int dx = -3; dx <= 3; dx++) {
                if (dy == 0 && dx == 0) continue;
                int qx = x + dx, qy = y + dy;
                const bool oob = ((unsigned)qx >= (unsigned)WW) ||
                                 ((unsigned)qy >= (unsigned)HH);
                if (oob) {
                    qx = qx < 0 ? 0 : (qx >= WW ? WW - 1 : qx);
                    qy = qy < 0 ? 0 : (qy >= HH ? HH - 1 : qy);
                    const int q = (qy - y) * WW + (qx - x);  // rel to pidx

                    const float iq0 = __ldg(pi + q);
                    const float iq1 = __ldg(pi + q + HWSZ);
                    const float iq2 = __ldg(pi + q + 2 * HWSZ);
                    const float tq0 = __ldg(pt + q);
                    const float tq1 = __ldg(pt + q + HWSZ);
                    const float tq2 = __ldg(pt + q + 2 * HWSZ);

                    const float d0 = i0 - iq0, d1 = i1 - iq1, d2 = i2 - iq2;
                    const float e0 = t0 - tq0, e1 = t1 - tq1, e2 = t2 - tq2;

                    const float cd = fmaf(e0, e0, fmaf(e1, e1, e2 * e2));
                    const int ady = dy < 0 ? -dy : dy;
                    const int adx = dx < 0 ? -dx : dx;
                    const float ws = wky[ady] * wky[adx];
                    const float sconst = (float)(dy * dy + dx * dx) * INV2SS;
                    const float wcs = __expf(-fmaf(cd, INV2SC, sconst));

                    const float sm = lp_term(d0) + lp_term(d1) + lp_term(d2);
                    const float ed = lp_term(fabsf(d0) - fabsf(e0))
                                   + lp_term(fabsf(d1) - fabsf(e1))
                                   + lp_term(fabsf(d2) - fabsf(e2));

                    acc = fmaf(wcs, sm, acc);
                    acc = fmaf(ws - wcs, ed, acc);
                }
            }
        }
    }

    reduce_add(acc, out, threadIdx.x);
}

extern "C" void kernel_launch(void* const* d_in, const int* in_sizes, int n_in,
                              void* d_out, int out_size) {
    const float* inp = (const float*)d_in[0];
    const float* tgt = (const float*)d_in[1];
    float* out = (float*)d_out;

    init_kernel<<<1, 64>>>(out);

    border_kernel<<<(NBTOT + 255) / 256, 256>>>(inp, tgt, out);

    dim3 block(32, 8, 1);
    dim3 grid(WW / 32, HH / 8, BB);
    pair_kernel<<<grid, block>>>(inp, tgt, out);
}